// round 10
// baseline (speedup 1.0000x reference)
#include <cuda_runtime.h>
#include <math.h>
#include <stdint.h>

#define BB 16
#define DD 256
#define LL 200
#define TT 1000

// output layout (float32, flattened concat of reference tuple)
#define LS_OFF   4096000
#define FM_OFF   8192000
#define FL_OFF   8208000
#define W_OFF    8208016

#define NEG_INF (__int_as_float(0xff800000))

// -------- scratch (device globals; no allocations allowed) --------
__device__ float  g_sk[BB*LL];
__device__ int    g_flen[BB];
__device__ float  g_CW[2*8*3*DD];
__device__ float  g_bk[2*8*3];
__device__ float  g_h[2*BB*LL*8];      // [path][b][l][o]
__device__ float4 g_bw4[BB*LL];        // MLP-w base per (b,l)
__device__ float2 g_bc2[BB*LL];        // MLP-c base per (b,l)
__device__ float  g_phT[BB*LL*DD];     // [b*l][d]
__device__ float  g_P[BB*LL*4*DD];     // [b][l][q][e]
__device__ float  g_Wscr[BB*TT*LL*4];  // [b][t][l*4+q] (BSS zero; rows >= fl never written)
__device__ float  g_part[BB*TT*DD];
__device__ float  g_whc[BB*TT*DD];

__device__ __forceinline__ float siluf(float x) { return x / (1.f + __expf(-x)); }

__device__ __forceinline__ float2 u2f(unsigned long long v) {
    float2 f;
    asm("mov.b64 {%0, %1}, %2;" : "=f"(f.x), "=f"(f.y) : "l"(v));
    return f;
}

// ============ 64x64 tile GEMM core: K-chunk 32, double-buffered, FFMA2 ============
// acc pairs over M (even/odd rows), B stored DUPLICATED in smem -> no packing movs
// inner loop: 1 LDS.128 (A pairs) + 2 LDS.128 (B dup) + 8 FFMA2 per kk.
__device__ __forceinline__ void gemm_mainloop(
    const float* __restrict__ A, int lda, int m0, int mmax,
    const float* __restrict__ B, int ldb, int n0, int K,
    float (*As)[2048], float (*Bs2)[4096],
    unsigned long long (&accp)[2][4])
{
    int tid = threadIdx.x;
    int arow = tid >> 2, akq = tid & 3;
    int bk = tid >> 3, bnq = tid & 7;
    int ty = tid >> 4, tx = tid & 15;
    int am = m0 + arow;
    bool aok = am < mmax;
    const float* Ap = A + (size_t)am*lda + akq*4;
    const float* Bp = B + (size_t)bk*ldb + n0 + bnq*8;
    int NC = K >> 5;
    float4 a0, a1, b0, b1;
    a0 = aok ? *(const float4*)(Ap)      : make_float4(0.f,0.f,0.f,0.f);
    a1 = aok ? *(const float4*)(Ap + 16) : make_float4(0.f,0.f,0.f,0.f);
    b0 = *(const float4*)(Bp);
    b1 = *(const float4*)(Bp + 4);
    {
        float* as = As[0]; float* bs = Bs2[0];
        as[(akq*4+0)*64 + arow] = a0.x;
        as[(akq*4+1)*64 + arow] = a0.y;
        as[(akq*4+2)*64 + arow] = a0.z;
        as[(akq*4+3)*64 + arow] = a0.w;
        as[(16+akq*4+0)*64 + arow] = a1.x;
        as[(16+akq*4+1)*64 + arow] = a1.y;
        as[(16+akq*4+2)*64 + arow] = a1.z;
        as[(16+akq*4+3)*64 + arow] = a1.w;
        float* bp = bs + bk*128 + bnq*16;
        *(float4*)(bp+0)  = make_float4(b0.x,b0.x,b0.y,b0.y);
        *(float4*)(bp+4)  = make_float4(b0.z,b0.z,b0.w,b0.w);
        *(float4*)(bp+8)  = make_float4(b1.x,b1.x,b1.y,b1.y);
        *(float4*)(bp+12) = make_float4(b1.z,b1.z,b1.w,b1.w);
    }
    for (int c = 0; c < NC; c++) {
        __syncthreads();
        int cur = c & 1;
        if (c + 1 < NC) {
            int k0 = (c + 1) << 5;
            a0 = aok ? *(const float4*)(Ap + k0)      : make_float4(0.f,0.f,0.f,0.f);
            a1 = aok ? *(const float4*)(Ap + k0 + 16) : make_float4(0.f,0.f,0.f,0.f);
            b0 = *(const float4*)(Bp + (size_t)k0*ldb);
            b1 = *(const float4*)(Bp + (size_t)k0*ldb + 4);
        }
        const float* as = As[cur];
        const float* bs = Bs2[cur];
        #pragma unroll
        for (int kk = 0; kk < 32; kk++) {
            ulonglong2 ap  = *(const ulonglong2*)&as[kk*64 + ty*4];
            ulonglong2 bq0 = *(const ulonglong2*)&bs[kk*128 + tx*8];
            ulonglong2 bq1 = *(const ulonglong2*)&bs[kk*128 + tx*8 + 4];
            asm("fma.rn.f32x2 %0, %1, %2, %0;" : "+l"(accp[0][0]) : "l"(ap.x), "l"(bq0.x));
            asm("fma.rn.f32x2 %0, %1, %2, %0;" : "+l"(accp[0][1]) : "l"(ap.x), "l"(bq0.y));
            asm("fma.rn.f32x2 %0, %1, %2, %0;" : "+l"(accp[0][2]) : "l"(ap.x), "l"(bq1.x));
            asm("fma.rn.f32x2 %0, %1, %2, %0;" : "+l"(accp[0][3]) : "l"(ap.x), "l"(bq1.y));
            asm("fma.rn.f32x2 %0, %1, %2, %0;" : "+l"(accp[1][0]) : "l"(ap.y), "l"(bq0.x));
            asm("fma.rn.f32x2 %0, %1, %2, %0;" : "+l"(accp[1][1]) : "l"(ap.y), "l"(bq0.y));
            asm("fma.rn.f32x2 %0, %1, %2, %0;" : "+l"(accp[1][2]) : "l"(ap.y), "l"(bq1.x));
            asm("fma.rn.f32x2 %0, %1, %2, %0;" : "+l"(accp[1][3]) : "l"(ap.y), "l"(bq1.y));
        }
        if (c + 1 < NC) {
            float* asn = As[cur^1]; float* bsn = Bs2[cur^1];
            asn[(akq*4+0)*64 + arow] = a0.x;
            asn[(akq*4+1)*64 + arow] = a0.y;
            asn[(akq*4+2)*64 + arow] = a0.z;
            asn[(akq*4+3)*64 + arow] = a0.w;
            asn[(16+akq*4+0)*64 + arow] = a1.x;
            asn[(16+akq*4+1)*64 + arow] = a1.y;
            asn[(16+akq*4+2)*64 + arow] = a1.z;
            asn[(16+akq*4+3)*64 + arow] = a1.w;
            float* bp = bsn + bk*128 + bnq*16;
            *(float4*)(bp+0)  = make_float4(b0.x,b0.x,b0.y,b0.y);
            *(float4*)(bp+4)  = make_float4(b0.z,b0.z,b0.w,b0.w);
            *(float4*)(bp+8)  = make_float4(b1.x,b1.x,b1.y,b1.y);
            *(float4*)(bp+12) = make_float4(b1.z,b1.z,b1.w,b1.w);
        }
    }
}

// unpack accp into 4 row-vectors of 4 n-values
__device__ __forceinline__ void unpack_rows(const unsigned long long (&accp)[2][4],
                                            float4 (&rows)[4]) {
    #pragma unroll
    for (int mp = 0; mp < 2; mp++) {
        float2 q0 = u2f(accp[mp][0]);
        float2 q1 = u2f(accp[mp][1]);
        float2 q2 = u2f(accp[mp][2]);
        float2 q3 = u2f(accp[mp][3]);
        rows[mp*2+0] = make_float4(q0.x, q1.x, q2.x, q3.x);
        rows[mp*2+1] = make_float4(q0.y, q1.y, q2.y, q3.y);
    }
}

// ---------------- K1: scan durations, frame lengths/mask ----------------
__global__ void k_setup(const float* __restrict__ dur, float* __restrict__ out) {
    int b = blockIdx.x, tid = threadIdx.x;
    __shared__ float s[256];
    __shared__ double ds[256];
    __shared__ int sfl;
    float d = (tid < LL) ? dur[b*LL + tid] : 0.f;
    s[tid] = d;
    for (int off = 1; off < 256; off <<= 1) {
        __syncthreads();
        float v = (tid >= off) ? s[tid - off] : 0.f;
        __syncthreads();
        s[tid] += v;
    }
    __syncthreads();
    if (tid < LL) g_sk[b*LL + tid] = s[tid] - d;
    ds[tid] = (double)d;
    __syncthreads();
    for (int off = 128; off > 0; off >>= 1) {
        if (tid < off) ds[tid] += ds[tid + off];
        __syncthreads();
    }
    if (tid == 0) {
        int fl = (int)rint(ds[0]);
        if (fl < 0) fl = 0;
        if (fl > TT) fl = TT;
        g_flen[b] = fl;
        out[FL_OFF + b] = (float)fl;
        sfl = fl;
    }
    __syncthreads();
    int fl = sfl;
    for (int t = tid; t < TT; t += 256)
        out[FM_OFF + b*TT + t] = (t < fl) ? 1.f : 0.f;
}

// ---------------- K2: fold conv kernels with pointwise weight ----------------
__global__ void k_fold(const float* __restrict__ Cw, const float* __restrict__ Wpw,
                       const float* __restrict__ bpw, const float* __restrict__ Cc,
                       const float* __restrict__ Wpc, const float* __restrict__ bpc) {
    int blk = blockIdx.x;
    int p = blk / 24, r = blk % 24, o = r / 3, k = r % 3;
    const float* Cm = p ? Cc : Cw;
    const float* Wp = p ? Wpc : Wpw;
    const float* bp = p ? bpc : bpw;
    int dp = threadIdx.x;
    float s = 0.f;
    for (int d = 0; d < DD; d++)
        s += Cm[(o*DD + d)*3 + k] * Wp[d*DD + dp];
    g_CW[((p*8 + o)*3 + k)*DD + dp] = s;
    if (dp == 0) {
        float bs = 0.f;
        for (int d = 0; d < DD; d++) bs += Cm[(o*DD + d)*3 + k] * bp[d];
        g_bk[(p*8 + o)*3 + k] = bs;
    }
}

// ---------------- K3: h_w / h_c (folded conv + silu + mask) ----------------
__global__ void k_conv(const float* __restrict__ ph, const float* __restrict__ dur,
                       const float* __restrict__ cbw, const float* __restrict__ cbc) {
    int bl = blockIdx.x;
    int b = bl / LL, l = bl % LL;
    __shared__ float sph[3*DD];
    int tid = threadIdx.x;
    for (int i = tid; i < 3*DD; i += 512) {
        int k = i / DD, d = i % DD;
        int ll = l + k - 1;
        sph[i] = (ll >= 0 && ll < LL) ? ph[(b*DD + d)*LL + ll] : 0.f;
    }
    __syncthreads();
    int wid = tid / 32, lane = tid % 32;
    float s = 0.f;
    const float* cw = &g_CW[wid*3*DD];
    for (int i = lane; i < 3*DD; i += 32) s += cw[i] * sph[i];
    #pragma unroll
    for (int off = 16; off > 0; off >>= 1) s += __shfl_down_sync(0xffffffffu, s, off);
    if (lane == 0) {
        int p = wid / 8, o = wid % 8;
        float bias = p ? cbc[o] : cbw[o];
        #pragma unroll
        for (int k = 0; k < 3; k++) {
            int ll = l + k - 1;
            if (ll >= 0 && ll < LL) bias += g_bk[wid*3 + k];
        }
        float h = siluf(s + bias);
        bool pm = dur[b*LL + l] > 0.f;
        g_h[((p*BB + b)*LL + l)*8 + o] = pm ? h : 0.f;
    }
}

// ---------------- K3b: hoist per-(b,l) affine base of the MLPs ----------------
__global__ void k_base(const float* __restrict__ dur,
                       const float* __restrict__ Mw, const float* __restrict__ mbw,
                       const float* __restrict__ Mc, const float* __restrict__ mbc) {
    int b = blockIdx.x, l = threadIdx.x;
    if (l >= LL) return;
    float d  = dur[b*LL + l];
    float sk = g_sk[b*LL + l];
    const float* hw = &g_h[((0*BB + b)*LL + l)*8];
    const float* hc = &g_h[((1*BB + b)*LL + l)*8];
    float bw[4];
    #pragma unroll
    for (int q = 0; q < 4; q++) {
        float a = mbw[q] - sk*Mw[0*4+q] + d*Mw[1*4+q];
        #pragma unroll
        for (int o = 0; o < 8; o++) a += hw[o]*Mw[(2+o)*4 + q];
        bw[q] = a;
    }
    g_bw4[b*LL + l] = make_float4(bw[0], bw[1], bw[2], bw[3]);
    float bc[2];
    #pragma unroll
    for (int p = 0; p < 2; p++) {
        float a = mbc[p] - sk*Mc[0*2+p] + d*Mc[1*2+p];
        #pragma unroll
        for (int o = 0; o < 8; o++) a += hc[o]*Mc[(2+o)*2 + p];
        bc[p] = a;
    }
    g_bc2[b*LL + l] = make_float2(bc[0], bc[1]);
}

// ---------------- K4t: transpose phoneme to [b][l][d] ----------------
__global__ void k_transpose(const float* __restrict__ ph) {
    __shared__ float tile[32][33];
    int b = blockIdx.z;
    int l0 = blockIdx.x * 32, d0 = blockIdx.y * 32;
    int tx = threadIdx.x, ty = threadIdx.y;
    #pragma unroll
    for (int j = 0; j < 32; j += 8) {
        int d = d0 + ty + j, l = l0 + tx;
        tile[ty + j][tx] = (l < LL) ? ph[(b*DD + d)*LL + l] : 0.f;
    }
    __syncthreads();
    #pragma unroll
    for (int j = 0; j < 32; j += 8) {
        int l = l0 + ty + j, d = d0 + tx;
        if (l < LL) g_phT[(b*LL + l)*DD + d] = tile[tx][ty + j];
    }
}

// ---------------- K4: P[b,l,q,e] = phT @ Lw_q ----------------
__global__ void __launch_bounds__(256) k_gemm_P(const float* __restrict__ Lw) {
    __shared__ __align__(16) float As[2][2048];
    __shared__ __align__(16) float Bs2[2][4096];
    int n0 = blockIdx.x*64, m0 = blockIdx.y*64, q = blockIdx.z;
    unsigned long long accp[2][4] = {};
    gemm_mainloop(g_phT, 256, m0, BB*LL, Lw + q*DD*DD, 256, n0, 256, As, Bs2, accp);
    float4 rows[4];
    unpack_rows(accp, rows);
    int ty = threadIdx.x >> 4, tx = threadIdx.x & 15;
    #pragma unroll
    for (int r = 0; r < 4; r++) {
        int m = m0 + ty*4 + r;
        *(float4*)&g_P[((size_t)m*4 + q)*DD + n0 + tx*4] = rows[r];
    }
}

// ---------------- K5a: MLPs + softmax + w outputs + small-path (warp per t) ----------------
__global__ void __launch_bounds__(256) k_wsoft(
        const float* __restrict__ dur,
        const float* __restrict__ Mw, const float* __restrict__ Mc,
        const float* __restrict__ Lc,
        const float* __restrict__ lbw, const float* __restrict__ lbc,
        float* __restrict__ out) {
    int b = blockIdx.y;
    int w = threadIdx.x >> 5, lane = threadIdx.x & 31;
    int t = blockIdx.x*8 + w;
    int fl = g_flen[b];
    float* w_out = out + W_OFF;
    size_t wbase = ((size_t)b*4*TT + t)*LL;
    if (t >= fl) {
        #pragma unroll
        for (int q = 0; q < 4; q++)
            #pragma unroll
            for (int i = 0; i < 7; i++) {
                int l = i*32 + lane;
                if (l < LL) w_out[wbase + (size_t)q*TT*LL + l] = 0.f;
            }
        return;
    }
    float tp1 = (float)(t + 1);
    float mw0 = Mw[0], mw1 = Mw[1], mw2 = Mw[2], mw3 = Mw[3];
    float mc0 = Mc[0], mc1 = Mc[1];
    float lw[7][4], ccv[7][2];
    float mx0 = NEG_INF, mx1 = NEG_INF, mx2 = NEG_INF, mx3 = NEG_INF;
    #pragma unroll
    for (int i = 0; i < 7; i++) {
        int l = i*32 + lane;
        bool vld = l < LL;
        float d = vld ? dur[b*LL + l] : 0.f;
        bool pm = d > 0.f;
        float4 bw = vld ? g_bw4[b*LL + l] : make_float4(0.f,0.f,0.f,0.f);
        float2 bc = vld ? g_bc2[b*LL + l] : make_float2(0.f,0.f);
        float v0 = siluf(fmaf(tp1, mw0, bw.x));
        float v1 = siluf(fmaf(tp1, mw1, bw.y));
        float v2 = siluf(fmaf(tp1, mw2, bw.z));
        float v3 = siluf(fmaf(tp1, mw3, bw.w));
        lw[i][0] = pm ? v0 : NEG_INF;
        lw[i][1] = pm ? v1 : NEG_INF;
        lw[i][2] = pm ? v2 : NEG_INF;
        lw[i][3] = pm ? v3 : NEG_INF;
        ccv[i][0] = siluf(fmaf(tp1, mc0, bc.x));
        ccv[i][1] = siluf(fmaf(tp1, mc1, bc.y));
        mx0 = fmaxf(mx0, lw[i][0]);
        mx1 = fmaxf(mx1, lw[i][1]);
        mx2 = fmaxf(mx2, lw[i][2]);
        mx3 = fmaxf(mx3, lw[i][3]);
    }
    #pragma unroll
    for (int off = 16; off > 0; off >>= 1) {
        mx0 = fmaxf(mx0, __shfl_xor_sync(0xffffffffu, mx0, off));
        mx1 = fmaxf(mx1, __shfl_xor_sync(0xffffffffu, mx1, off));
        mx2 = fmaxf(mx2, __shfl_xor_sync(0xffffffffu, mx2, off));
        mx3 = fmaxf(mx3, __shfl_xor_sync(0xffffffffu, mx3, off));
    }
    float s0 = 0.f, s1 = 0.f, s2 = 0.f, s3 = 0.f;
    float exc[8] = {0.f,0.f,0.f,0.f,0.f,0.f,0.f,0.f};
    #pragma unroll
    for (int i = 0; i < 7; i++) {
        float e0 = __expf(lw[i][0] - mx0);
        float e1 = __expf(lw[i][1] - mx1);
        float e2 = __expf(lw[i][2] - mx2);
        float e3 = __expf(lw[i][3] - mx3);
        lw[i][0] = e0; lw[i][1] = e1; lw[i][2] = e2; lw[i][3] = e3;
        s0 += e0; s1 += e1; s2 += e2; s3 += e3;
        float c0 = ccv[i][0], c1 = ccv[i][1];
        exc[0] += e0*c0; exc[1] += e0*c1;
        exc[2] += e1*c0; exc[3] += e1*c1;
        exc[4] += e2*c0; exc[5] += e2*c1;
        exc[6] += e3*c0; exc[7] += e3*c1;
    }
    #pragma unroll
    for (int off = 16; off > 0; off >>= 1) {
        s0 += __shfl_xor_sync(0xffffffffu, s0, off);
        s1 += __shfl_xor_sync(0xffffffffu, s1, off);
        s2 += __shfl_xor_sync(0xffffffffu, s2, off);
        s3 += __shfl_xor_sync(0xffffffffu, s3, off);
        #pragma unroll
        for (int j = 0; j < 8; j++)
            exc[j] += __shfl_xor_sync(0xffffffffu, exc[j], off);
    }
    float i0 = 1.f/s0, i1 = 1.f/s1, i2 = 1.f/s2, i3 = 1.f/s3;
    #pragma unroll
    for (int i = 0; i < 7; i++) {
        int l = i*32 + lane;
        if (l < LL) {
            float w0 = lw[i][0]*i0, w1 = lw[i][1]*i1, w2 = lw[i][2]*i2, w3 = lw[i][3]*i3;
            w_out[wbase + 0*(size_t)TT*LL + l] = w0;
            w_out[wbase + 1*(size_t)TT*LL + l] = w1;
            w_out[wbase + 2*(size_t)TT*LL + l] = w2;
            w_out[wbase + 3*(size_t)TT*LL + l] = w3;
            *(float4*)&g_Wscr[((size_t)b*TT + t)*800 + l*4] = make_float4(w0, w1, w2, w3);
        }
    }
    float wc[8];
    wc[0] = exc[0]*i0; wc[1] = exc[1]*i0;
    wc[2] = exc[2]*i1; wc[3] = exc[3]*i1;
    wc[4] = exc[4]*i2; wc[5] = exc[5]*i2;
    wc[6] = exc[6]*i3; wc[7] = exc[7]*i3;
    #pragma unroll
    for (int j = 0; j < 8; j++) {
        int e = j*32 + lane;
        float acc = lbw[e] + lbc[e];
        #pragma unroll
        for (int qp = 0; qp < 8; qp++) acc = fmaf(wc[qp], Lc[qp*DD + e], acc);
        g_part[((size_t)b*TT + t)*DD + e] = acc;
    }
}

// ---------------- K5b: whc = W(1000x800) @ P_b(800x256) + part, masked ----------------
__global__ void __launch_bounds__(256) k_gemm_whc() {
    __shared__ __align__(16) float As[2][2048];
    __shared__ __align__(16) float Bs2[2][4096];
    int n0 = blockIdx.x*64, m0 = blockIdx.y*64, b = blockIdx.z;
    int fl = g_flen[b];
    int ty = threadIdx.x >> 4, tx = threadIdx.x & 15;
    if (m0 >= fl) {
        #pragma unroll
        for (int r = 0; r < 4; r++) {
            int m = m0 + ty*4 + r;
            if (m < TT)
                *(float4*)&g_whc[((size_t)b*TT + m)*DD + n0 + tx*4] =
                    make_float4(0.f, 0.f, 0.f, 0.f);
        }
        return;
    }
    unsigned long long accp[2][4] = {};
    gemm_mainloop(g_Wscr + (size_t)b*TT*800, 800, m0, TT,
                  g_P + (size_t)b*LL*4*DD, 256, n0, 800, As, Bs2, accp);
    float4 rows[4];
    unpack_rows(accp, rows);
    #pragma unroll
    for (int r = 0; r < 4; r++) {
        int m = m0 + ty*4 + r;
        if (m < TT) {
            float4 v = make_float4(0.f, 0.f, 0.f, 0.f);
            if (m < fl) {
                float4 p = *(const float4*)&g_part[((size_t)b*TT + m)*DD + n0 + tx*4];
                v = make_float4(rows[r].x + p.x, rows[r].y + p.y,
                                rows[r].z + p.z, rows[r].w + p.w);
            }
            *(float4*)&g_whc[((size_t)b*TT + m)*DD + n0 + tx*4] = v;
        }
    }
}

// ---------------- K5c: out = whc(16000x256) @ Wo(256x512) + bo, transposed write ----------------
__global__ void __launch_bounds__(256) k_gemm_out(const float* __restrict__ Wo,
                                                  const float* __restrict__ bo,
                                                  float* __restrict__ out) {
    __shared__ __align__(16) float As[2][2048];
    __shared__ __align__(16) float Bs2[2][4096];
    int n0 = blockIdx.x*64, m0 = blockIdx.y*64;
    int ty = threadIdx.x >> 4, tx = threadIdx.x & 15;
    // early-out: whole tile in one batch AND above its frame length -> bias only
    {
        int b0 = m0 / TT, b1 = (m0 + 63) / TT;
        if (b0 == b1 && (m0 - b0*TT) >= g_flen[b0]) {
            #pragma unroll
            for (int j = 0; j < 4; j++) {
                int o = n0 + tx*4 + j;
                float bj = bo[o];
                #pragma unroll
                for (int r = 0; r < 4; r++) {
                    int m = m0 + ty*4 + r;
                    int b = m / TT, t = m % TT;
                    if (o < 256) out[((size_t)b*256 + o)*TT + t] = bj;
                    else         out[LS_OFF + ((size_t)b*256 + (o - 256))*TT + t] = bj;
                }
            }
            return;
        }
    }
    unsigned long long accp[2][4] = {};
    gemm_mainloop(g_whc, 256, m0, BB*TT, Wo, 512, n0, 256, As, Bs2, accp);
    float4 rows[4];
    unpack_rows(accp, rows);
    #pragma unroll
    for (int r = 0; r < 4; r++) {
        int m = m0 + ty*4 + r;
        int b = m / TT, t = m % TT;
        float vv[4] = {rows[r].x, rows[r].y, rows[r].z, rows[r].w};
        #pragma unroll
        for (int j = 0; j < 4; j++) {
            int o = n0 + tx*4 + j;
            float v = vv[j] + bo[o];
            if (o < 256) out[((size_t)b*256 + o)*TT + t] = v;
            else         out[LS_OFF + ((size_t)b*256 + (o - 256))*TT + t] = v;
        }
    }
}

extern "C" void kernel_launch(void* const* d_in, const int* in_sizes, int n_in,
                              void* d_out, int out_size) {
    const float* dur = (const float*)d_in[0];
    const float* ph  = (const float*)d_in[1];
    const float* Wpw = (const float*)d_in[3];
    const float* bpw = (const float*)d_in[4];
    const float* Cw  = (const float*)d_in[5];
    const float* cbw = (const float*)d_in[6];
    const float* Mw  = (const float*)d_in[7];
    const float* mbw = (const float*)d_in[8];
    const float* Lw  = (const float*)d_in[9];
    const float* lbw = (const float*)d_in[10];
    const float* Wpc = (const float*)d_in[11];
    const float* bpc = (const float*)d_in[12];
    const float* Cc  = (const float*)d_in[13];
    const float* cbc = (const float*)d_in[14];
    const float* Mc  = (const float*)d_in[15];
    const float* mbc = (const float*)d_in[16];
    const float* Lc  = (const float*)d_in[17];
    const float* lbc = (const float*)d_in[18];
    const float* Wo  = (const float*)d_in[19];
    const float* bo  = (const float*)d_in[20];
    float* out = (float*)d_out;

    k_setup<<<BB, 256>>>(dur, out);
    k_fold<<<48, 256>>>(Cw, Wpw, bpw, Cc, Wpc, bpc);
    k_conv<<<BB*LL, 512>>>(ph, dur, cbw, cbc);
    k_base<<<BB, 256>>>(dur, Mw, mbw, Mc, mbc);
    k_transpose<<<dim3(7, 8, BB), dim3(32, 8)>>>(ph);
    k_gemm_P<<<dim3(4, 50, 4), 256>>>(Lw);
    k_wsoft<<<dim3(125, BB), 256>>>(dur, Mw, Mc, Lc, lbw, lbc, out);
    k_gemm_whc<<<dim3(4, 16, BB), 256>>>();
    k_gemm_out<<<dim3(8, 250), 256>>>(Wo, bo, out);
}